// round 3
// baseline (speedup 1.0000x reference)
#include <cuda_runtime.h>
#include <math.h>
#include <stdint.h>

#define NGRAPH 32
#define NNODE  1024
#define CDIM   64
#define KTOP   16
#define NROWS  (NGRAPH * NNODE)            // 32768
#define OUT_ELEMS (NROWS * CDIM)           // 2097152
#define ROWS_OFF  OUT_ELEMS
#define COLS_OFF  (OUT_ELEMS + NROWS * KTOP)

__device__ float g_sq[NROWS];

// ---------------------------------------------------------------------------
// Encoder: out[32768,64] = x[32768,128] @ W[128,64] + b
// ---------------------------------------------------------------------------
__global__ void __launch_bounds__(256) enc_kernel(const float* __restrict__ x,
                                                  const float* __restrict__ W,
                                                  const float* __restrict__ b,
                                                  float* __restrict__ out) {
    __shared__ float sWt[64 * 132];   // W transposed [c][k], stride 132
    __shared__ float sX[16 * 128];    // 16-row strip of x
    int tid = threadIdx.x;
    int i0 = blockIdx.x * 16;

    for (int idx = tid; idx < 128 * 64; idx += 256) {
        int k = idx >> 6, c = idx & 63;
        sWt[c * 132 + k] = W[idx];
    }
    for (int idx = tid; idx < 16 * 128 / 4; idx += 256) {
        ((float4*)sX)[idx] = ((const float4*)(x + (size_t)i0 * 128))[idx];
    }
    __syncthreads();

    int c = tid & 63, ty = tid >> 6;
    float acc[4] = {0.f, 0.f, 0.f, 0.f};
    const float4* wt = (const float4*)(sWt + c * 132);
#pragma unroll
    for (int k4 = 0; k4 < 32; k4++) {
        float4 wv = wt[k4];
#pragma unroll
        for (int rr = 0; rr < 4; rr++) {
            float4 xv = ((const float4*)(sX + (ty + rr * 4) * 128))[k4];
            acc[rr] += xv.x * wv.x + xv.y * wv.y + xv.z * wv.z + xv.w * wv.w;
        }
    }
    float bc = b[c];
#pragma unroll
    for (int rr = 0; rr < 4; rr++) {
        out[(size_t)(i0 + ty + rr * 4) * 64 + c] = acc[rr] + bc;
    }
}

// ---------------------------------------------------------------------------
// Row squared norms: g_sq[row] = sum_c out[row][c]^2  (warp per row)
// ---------------------------------------------------------------------------
__global__ void __launch_bounds__(256) sq_kernel(const float* __restrict__ out) {
    int warp = (blockIdx.x * blockDim.x + threadIdx.x) >> 5;
    int lane = threadIdx.x & 31;
    if (warp >= NROWS) return;
    const float* p = out + (size_t)warp * 64;
    float a = p[lane], c = p[lane + 32];
    float s = a * a + c * c;
#pragma unroll
    for (int o = 16; o; o >>= 1) s += __shfl_xor_sync(0xffffffffu, s, o);
    if (lane == 0) g_sq[warp] = s;
}

// ---------------------------------------------------------------------------
// JAX threefry2x32 with key = jax.random.key(1) -> (k0,k1) = (0,1).
// Partitionable random_bits path (modern JAX default): per-element 64-bit
// counter e -> inputs (x0 = hi32(e) = 0 for e < 2^32, x1 = lo32(e)),
// result bits = o0 ^ o1.
// ---------------------------------------------------------------------------
__device__ __forceinline__ uint32_t threefry_bits_k01(uint32_t e) {
    const uint32_t ks0 = 0u, ks1 = 1u, ks2 = 0x1BD11BDBu;  // 0x1BD11BDA ^ 0 ^ 1
    uint32_t x0 = 0u + ks0;
    uint32_t x1 = e + ks1;
#define TF_ROUND(r) { x0 += x1; x1 = __funnelshift_l(x1, x1, (r)); x1 ^= x0; }
    TF_ROUND(13) TF_ROUND(15) TF_ROUND(26) TF_ROUND(6)
    x0 += ks1; x1 += ks2 + 1u;
    TF_ROUND(17) TF_ROUND(29) TF_ROUND(16) TF_ROUND(24)
    x0 += ks2; x1 += ks0 + 2u;
    TF_ROUND(13) TF_ROUND(15) TF_ROUND(26) TF_ROUND(6)
    x0 += ks0; x1 += ks1 + 3u;
    TF_ROUND(17) TF_ROUND(29) TF_ROUND(16) TF_ROUND(24)
    x0 += ks1; x1 += ks2 + 4u;
    TF_ROUND(13) TF_ROUND(15) TF_ROUND(26) TF_ROUND(6)
    x0 += ks2; x1 += ks0 + 5u;
#undef TF_ROUND
    return x0 ^ x1;
}

// gumbel = -log(-log(max(tiny, f + tiny))). Inner -log via log1pf(u-1):
// exact in the u->1 region that top-k actually selects, and immune to a
// fast-math remap of logf for the inner call.
__device__ __forceinline__ float gumbel_from_bits(uint32_t bits) {
    const float TINY = 1.17549435e-38f;
    float f = __uint_as_float((bits >> 9) | 0x3f800000u) - 1.0f;
    float u = fmaxf(TINY, f + TINY);
    float w = -log1pf(u - 1.0f);     // == -log(u), accurate near u=1
    return -logf(w);
}

// ---------------------------------------------------------------------------
// Fused: pairwise dist + logits + gumbel + top-16 per row.
// Block = (graph g, 16-row i-strip), 256 threads. grid = (32, 64).
// j tiled by 64 through shared memory; threshold-filtered shared-atomic
// candidate append, merged by 16 leader threads.
// ---------------------------------------------------------------------------
#define TI 16
#define TJ 64
#define SSTRIDE 68    // float stride, conflict-free for LDS.128

__global__ void __launch_bounds__(256) dgm_kernel(float* __restrict__ buf,
                                                  const float* __restrict__ tptr) {
    __shared__ float sA[TI * SSTRIDE];
    __shared__ float sB[TJ * SSTRIDE];
    __shared__ float sqI[TI];
    __shared__ float sqJ[TJ];
    __shared__ float candV[TI * 64];
    __shared__ float topV[TI * KTOP];
    __shared__ float thr[TI];
    __shared__ int   candI[TI * 64];
    __shared__ int   topI[TI * KTOP];
    __shared__ int   cnt[TI];

    const float* h = buf;                 // encoder output region of d_out
    int tid = threadIdx.x;
    int g   = blockIdx.x;
    int i0  = blockIdx.y * TI;
    int gbase = g * NNODE;

    // ---- init ----
    for (int idx = tid; idx < TI * 16; idx += 256) {
        int r = idx >> 4, k4 = idx & 15;
        float4 v = ((const float4*)(h + (size_t)(gbase + i0 + r) * 64))[k4];
        float* dst = sA + r * SSTRIDE + k4 * 4;
        dst[0] = v.x; dst[1] = v.y; dst[2] = v.z; dst[3] = v.w;
    }
    if (tid < TI) {
        sqI[tid] = g_sq[gbase + i0 + tid];
        thr[tid] = -INFINITY;
        cnt[tid] = 0;
    }
    if (tid < TI * KTOP) { topV[tid] = -INFINITY; topI[tid] = 0; }

    float nT = -(*tptr);
    int j = tid & 63;                     // j within tile
    int q = tid >> 6;                     // i-group (4 rows each)
    uint32_t ebase_row = ((uint32_t)g << 20) + ((uint32_t)(i0 + q * 4) << 10);

    for (int jt = 0; jt < NNODE / TJ; jt++) {
        int j0 = jt * TJ;
        for (int idx = tid; idx < TJ * 16; idx += 256) {
            int r = idx >> 4, k4 = idx & 15;
            float4 v = ((const float4*)(h + (size_t)(gbase + j0 + r) * 64))[k4];
            float* dst = sB + r * SSTRIDE + k4 * 4;
            dst[0] = v.x; dst[1] = v.y; dst[2] = v.z; dst[3] = v.w;
        }
        if (tid < TJ) sqJ[tid] = g_sq[gbase + j0 + tid];
        __syncthreads();

        // ---- dot products: 4 i's for this thread's j ----
        float dot[4] = {0.f, 0.f, 0.f, 0.f};
        const float* pj = sB + j * SSTRIDE;
        const float* pi = sA + (q * 4) * SSTRIDE;
#pragma unroll
        for (int k4 = 0; k4 < 16; k4++) {
            float4 a = *(const float4*)(pj + k4 * 4);
#pragma unroll
            for (int ii = 0; ii < 4; ii++) {
                float4 c = *(const float4*)(pi + ii * SSTRIDE + k4 * 4);
                dot[ii] += c.x * a.x + c.y * a.y + c.z * a.z + c.w * a.w;
            }
        }

        uint32_t jg = (uint32_t)(j0 + j);
#pragma unroll
        for (int ii = 0; ii < 4; ii++) {
            int li = q * 4 + ii;
            // d = (sq_i + sq_j) - 2*dot, XLA-matching elementwise rounding
            float s  = __fadd_rn(sqI[li], sqJ[j]);
            float d  = __fadd_rn(s, -__fmul_rn(2.0f, dot[ii]));
            float lg = expf(__fmul_rn(nT, d));
            uint32_t e = ebase_row + ((uint32_t)ii << 10) + jg;
            float v = lg + gumbel_from_bits(threefry_bits_k01(e));
            if (v > thr[li]) {
                int p = atomicAdd(&cnt[li], 1);
                candV[li * 64 + p] = v;
                candI[li * 64 + p] = (int)jg;
            }
        }
        __syncthreads();

        // ---- leaders merge candidates into sorted top-16, raise threshold ----
        if (tid < TI) {
            int r = tid, c = cnt[r];
            float* tv = topV + r * KTOP;
            int*   ti = topI + r * KTOP;
            for (int m = 0; m < c; m++) {
                float v = candV[r * 64 + m];
                if (v > tv[KTOP - 1]) {
                    int id = candI[r * 64 + m];
                    int p = KTOP - 1;
                    while (p > 0 && tv[p - 1] < v) {
                        tv[p] = tv[p - 1]; ti[p] = ti[p - 1]; p--;
                    }
                    tv[p] = v; ti[p] = id;
                }
            }
            cnt[r] = 0;
            thr[r] = tv[KTOP - 1];
        }
        __syncthreads();
    }

    // ---- write edges (indices as float) ----
    if (tid < TI) {
        int grow = gbase + i0 + tid;
        size_t base = (size_t)grow * KTOP;
        float rowv = (float)grow;
#pragma unroll
        for (int k = 0; k < KTOP; k++) {
            buf[ROWS_OFF + base + k] = rowv;
            buf[COLS_OFF + base + k] = (float)(gbase + topI[tid * KTOP + k]);
        }
    }
}

// ---------------------------------------------------------------------------
extern "C" void kernel_launch(void* const* d_in, const int* in_sizes, int n_in,
                              void* d_out, int out_size) {
    const float* x    = (const float*)d_in[0];
    const float* W    = (const float*)d_in[1];
    const float* b    = (const float*)d_in[2];
    const float* temp = (const float*)d_in[3];
    float* out = (float*)d_out;

    enc_kernel<<<NROWS / 16, 256>>>(x, W, b, out);
    sq_kernel<<<NROWS / 8, 256>>>(out);
    dgm_kernel<<<dim3(NGRAPH, NNODE / TI), 256>>>(out, temp);
}